// round 13
// baseline (speedup 1.0000x reference)
#include <cuda_runtime.h>
#include <cuda_fp16.h>
#include <cstdint>

#define N_NODES 100000
#define IN_CH   512
#define HID     16
#define OUT_CH  64
#define MAX_E   3200000
#define NBLK    ((N_NODES + 255) / 256)   // 391 scan blocks

typedef unsigned long long u64;

// ---------------- device scratch (static, no allocation) ----------------
__device__ float   g_dinv[N_NODES];
__device__ int     g_cnt[N_NODES];
__device__ u64     g_bstate[NBLK];        // decoupled-lookback state
__device__ int     g_rowptr[N_NODES + 1];
__device__ int     g_cur[N_NODES];
__device__ int     g_csr[MAX_E];          // src only, bucketed by dst
__device__ __half2 g_h1h[N_NODES * 8];    // h1' = (x@W1)*dinv, fp16 (32B/row)
__device__ __half2 g_hrh[N_NODES * 8];    // hr' = relu(conv1)*dinv, fp16

// ---------------- f32x2 / cp.async helpers ----------------
__device__ __forceinline__ u64 pack2(float lo, float hi) {
    u64 r; asm("mov.b64 %0, {%1, %2};" : "=l"(r) : "f"(lo), "f"(hi)); return r;
}
__device__ __forceinline__ u64 fma2(u64 a, u64 b, u64 c) {
    u64 d; asm("fma.rn.f32x2 %0, %1, %2, %3;" : "=l"(d) : "l"(a), "l"(b), "l"(c)); return d;
}
__device__ __forceinline__ float2 unpack2(u64 v) {
    float2 f; asm("mov.b64 {%0, %1}, %2;" : "=f"(f.x), "=f"(f.y) : "l"(v)); return f;
}
__device__ __forceinline__ void cpasync16(uint32_t saddr, const void* g, int srcbytes) {
    asm volatile("cp.async.cg.shared.global [%0], [%1], 16, %2;"
                 :: "r"(saddr), "l"(g), "r"(srcbytes));
}
__device__ __forceinline__ void cp_commit() {
    asm volatile("cp.async.commit_group;");
}
template <int N>
__device__ __forceinline__ void cp_wait() {
    asm volatile("cp.async.wait_group %0;" :: "n"(N));
}

// ---------------- GEMM1: h1' = (x @ W1) * dinv -> fp16 table ----------------
#define XS_PITCH 20
#define NCHUNK   (IN_CH / 16)   // 32
__global__ void __launch_bounds__(256, 3) k_gemm1(const float* __restrict__ x,
                                                  const float* __restrict__ W, int n) {
    __shared__ __align__(16) float xs[2][256 * XS_PITCH];  // 2 x 20 KB
    __shared__ __align__(16) u64   wp[2][8 * HID];         // 2 x 1 KB

    const int t = threadIdx.x;
    const int rowBase = blockIdx.x * 256;
    const int rg = t >> 2;
    const int jg = t & 3;
    const int ko = (t & 3) * 4;

    auto stage_x = [&](int kk, int b) {
#pragma unroll
        for (int p = 0; p < 4; p++) {
            int row = (t >> 2) + p * 64;
            int grow = rowBase + row;
            bool ok = (grow < n);
            const float* gp = ok ? &x[(size_t)grow * IN_CH + kk + ko] : x;
            uint32_t sa = (uint32_t)__cvta_generic_to_shared(&xs[b][row * XS_PITCH + ko]);
            cpasync16(sa, gp, ok ? 16 : 0);
        }
    };
    auto stage_w = [&](int kk, int b) {
        if (t < 128) {
            int kp = t >> 4, j = t & 15;
            wp[b][kp * HID + j] = pack2(W[(kk + 2 * kp) * HID + j],
                                        W[(kk + 2 * kp + 1) * HID + j]);
        }
    };

    u64 acc[4][4];
#pragma unroll
    for (int r = 0; r < 4; r++)
#pragma unroll
        for (int j = 0; j < 4; j++) acc[r][j] = 0ull;

    stage_x(0, 0);
    stage_w(0, 0);
    cp_commit();

    int buf = 0;
    for (int c = 0; c < NCHUNK; c++) {
        if (c < NCHUNK - 1) {
            stage_x((c + 1) * 16, buf ^ 1);
            stage_w((c + 1) * 16, buf ^ 1);
            cp_commit();
            cp_wait<1>();
        } else {
            cp_wait<0>();
        }
        __syncthreads();

#pragma unroll
        for (int k4 = 0; k4 < 4; k4++) {
            u64 w0[4], w1[4];
            *reinterpret_cast<ulonglong2*>(&w0[0]) =
                *reinterpret_cast<const ulonglong2*>(&wp[buf][(2 * k4) * HID + jg * 4]);
            *reinterpret_cast<ulonglong2*>(&w0[2]) =
                *reinterpret_cast<const ulonglong2*>(&wp[buf][(2 * k4) * HID + jg * 4 + 2]);
            *reinterpret_cast<ulonglong2*>(&w1[0]) =
                *reinterpret_cast<const ulonglong2*>(&wp[buf][(2 * k4 + 1) * HID + jg * 4]);
            *reinterpret_cast<ulonglong2*>(&w1[2]) =
                *reinterpret_cast<const ulonglong2*>(&wp[buf][(2 * k4 + 1) * HID + jg * 4 + 2]);
#pragma unroll
            for (int r = 0; r < 4; r++) {
                ulonglong2 xq = *reinterpret_cast<const ulonglong2*>(
                    &xs[buf][(rg + 64 * r) * XS_PITCH + k4 * 4]);
#pragma unroll
                for (int j = 0; j < 4; j++) {
                    acc[r][j] = fma2(xq.x, w0[j], acc[r][j]);
                    acc[r][j] = fma2(xq.y, w1[j], acc[r][j]);
                }
            }
        }
        __syncthreads();
        buf ^= 1;
    }
#pragma unroll
    for (int r = 0; r < 4; r++) {
        int grow = rowBase + rg + 64 * r;
        if (grow < n) {
            float di = g_dinv[grow];
            float2 a0 = unpack2(acc[r][0]);
            float2 a1 = unpack2(acc[r][1]);
            float2 a2 = unpack2(acc[r][2]);
            float2 a3 = unpack2(acc[r][3]);
            __half2 h0 = __floats2half2_rn((a0.x + a0.y) * di, (a1.x + a1.y) * di);
            __half2 h1 = __floats2half2_rn((a2.x + a2.y) * di, (a3.x + a3.y) * di);
            // 8B store of two half2
            uint2 pk = make_uint2(*reinterpret_cast<uint32_t*>(&h0),
                                  *reinterpret_cast<uint32_t*>(&h1));
            *reinterpret_cast<uint2*>(&g_h1h[(size_t)grow * 8 + jg * 2]) = pk;
        }
    }
}

// ---------------- CSR build ----------------
__global__ void k_zero_cnt(int n) {
    int i = blockIdx.x * blockDim.x + threadIdx.x;
    if (i < n) g_cnt[i] = 0;
    if (i < NBLK) g_bstate[i] = 0ull;
}

__global__ void k_hist(const int* __restrict__ dst, int e) {
    int i = blockIdx.x * blockDim.x + threadIdx.x;
    if (i < e) atomicAdd(&g_cnt[dst[i]], 1);
}

// single-kernel exclusive scan via decoupled lookback (flag+value in one u64)
__global__ void __launch_bounds__(256) k_scan(int n) {
    __shared__ int s[256];
    __shared__ int s_prefix;
    const int t = threadIdx.x, b = blockIdx.x;
    const int i = b * 256 + t;
    int v = (i < n) ? g_cnt[i] : 0;
    s[t] = v;
    __syncthreads();
#pragma unroll
    for (int off = 1; off < 256; off <<= 1) {
        int add = (t >= off) ? s[t - off] : 0;
        __syncthreads();
        s[t] += add;
        __syncthreads();
    }
    int incl = s[t];
    int agg  = s[255];

    if (t == 0) {
        u64 pk = (b == 0) ? ((2ull << 40) | (unsigned)agg)
                          : ((1ull << 40) | (unsigned)agg);
        atomicExch(&g_bstate[b], pk);
        if (b == 0) s_prefix = 0;
    }
    if (b > 0 && t < 32) {
        int ex = 0;
        int base = b;
        while (true) {
            int p = base - 32 + t;
            u64 st = (p >= 0) ? atomicAdd(&g_bstate[p], 0ull) : (2ull << 40);
            int flag = (int)(st >> 40);
            int val  = (int)(st & 0xFFFFFFFFu);
            if (!__all_sync(0xffffffffu, flag != 0)) continue;
            unsigned pm = __ballot_sync(0xffffffffu, flag == 2);
            int hi = pm ? (31 - __clz(pm)) : 0;
            int contrib = (pm == 0 || t >= hi) ? val : 0;
#pragma unroll
            for (int o = 16; o; o >>= 1)
                contrib += __shfl_xor_sync(0xffffffffu, contrib, o);
            ex += contrib;
            if (pm) break;
            base -= 32;
        }
        if (t == 0) {
            s_prefix = ex;
            atomicExch(&g_bstate[b], (2ull << 40) | (unsigned)(ex + agg));
        }
    }
    __syncthreads();
    if (i < n) {
        int rp = s_prefix + incl - v;
        g_rowptr[i] = rp;
        g_cur[i] = rp;
        g_dinv[i] = rsqrtf((float)v + 1.0f);
        if (i == n - 1) g_rowptr[n] = rp + v;
    }
}

__global__ void k_scatter(const int* __restrict__ src,
                          const int* __restrict__ dst, int e) {
    int i = blockIdx.x * blockDim.x + threadIdx.x;
    if (i >= e) return;
    int d = dst[i];
    int pos = atomicAdd(&g_cur[d], 1);
    g_csr[pos] = src[i];
}

// ---------------- gather layer 1 (fp16 table in, fp16 table out) ----------------
__global__ void __launch_bounds__(256) k_gather1(const float* __restrict__ b1, int n) {
    int wid = (blockIdx.x * 256 + threadIdx.x) >> 5;
    if (wid >= n) return;
    int lane = threadIdx.x & 31;
    int ql = lane & 7, qh = lane >> 3;
    int row = g_rowptr[wid], end = g_rowptr[wid + 1];

    float2 acc = make_float2(0.f, 0.f);
    for (int i = row + qh; i < end; i += 4) {
        int s = g_csr[i];
        float2 f = __half22float2(g_h1h[(size_t)s * 8 + ql]);
        acc.x += f.x;
        acc.y += f.y;
    }
    acc.x += __shfl_xor_sync(0xffffffffu, acc.x, 8);
    acc.y += __shfl_xor_sync(0xffffffffu, acc.y, 8);
    acc.x += __shfl_xor_sync(0xffffffffu, acc.x, 16);
    acc.y += __shfl_xor_sync(0xffffffffu, acc.y, 16);

    float di = g_dinv[wid];
    float2 hv = __half22float2(g_h1h[(size_t)wid * 8 + ql]);
    float2 bb = *reinterpret_cast<const float2*>(&b1[ql * 2]);
    float rx = fmaxf(di * (acc.x + hv.x) + bb.x, 0.f) * di;
    float ry = fmaxf(di * (acc.y + hv.y) + bb.y, 0.f) * di;
    if (qh == 0)
        g_hrh[(size_t)wid * 8 + ql] = __floats2half2_rn(rx, ry);
}

// ---------------- gather layer 2 (fused W2 GEMM + log-softmax) ----------------
__global__ void __launch_bounds__(256) k_gather2(const float* __restrict__ W2,
                                                 const float* __restrict__ b2,
                                                 float* __restrict__ out, int n) {
    __shared__ float W2s[HID * OUT_CH];  // 4 KB
    for (int i = threadIdx.x; i < HID * OUT_CH; i += 256) W2s[i] = W2[i];
    __syncthreads();

    int wid = (blockIdx.x * 256 + threadIdx.x) >> 5;
    if (wid >= n) return;
    int lane = threadIdx.x & 31;
    int ql = lane & 7, qh = lane >> 3;
    int row = g_rowptr[wid], end = g_rowptr[wid + 1];

    float2 acc = make_float2(0.f, 0.f);
    for (int i = row + qh; i < end; i += 4) {
        int s = g_csr[i];
        float2 f = __half22float2(g_hrh[(size_t)s * 8 + ql]);
        acc.x += f.x;
        acc.y += f.y;
    }
    acc.x += __shfl_xor_sync(0xffffffffu, acc.x, 8);
    acc.y += __shfl_xor_sync(0xffffffffu, acc.y, 8);
    acc.x += __shfl_xor_sync(0xffffffffu, acc.x, 16);
    acc.y += __shfl_xor_sync(0xffffffffu, acc.y, 16);

    float di = g_dinv[wid];
    float2 hv = __half22float2(g_hrh[(size_t)wid * 8 + ql]);
    float tx = di * (acc.x + hv.x);
    float ty = di * (acc.y + hv.y);

    float y0 = b2[lane];
    float y1 = b2[lane + 32];
#pragma unroll
    for (int k = 0; k < 8; k++) {
        float a = __shfl_sync(0xffffffffu, tx, k);
        float b = __shfl_sync(0xffffffffu, ty, k);
        y0 += a * W2s[(2 * k) * OUT_CH + lane]      + b * W2s[(2 * k + 1) * OUT_CH + lane];
        y1 += a * W2s[(2 * k) * OUT_CH + lane + 32] + b * W2s[(2 * k + 1) * OUT_CH + lane + 32];
    }
    float m = fmaxf(y0, y1);
#pragma unroll
    for (int o = 16; o; o >>= 1) m = fmaxf(m, __shfl_xor_sync(0xffffffffu, m, o));
    float se = expf(y0 - m) + expf(y1 - m);
#pragma unroll
    for (int o = 16; o; o >>= 1) se += __shfl_xor_sync(0xffffffffu, se, o);
    float lg = m + logf(se);
    out[(size_t)wid * OUT_CH + lane]      = y0 - lg;
    out[(size_t)wid * OUT_CH + lane + 32] = y1 - lg;
}

// ---------------- launch ----------------
extern "C" void kernel_launch(void* const* d_in, const int* in_sizes, int n_in,
                              void* d_out, int out_size) {
    const float* x    = (const float*)d_in[0];
    const int*   ei   = (const int*)d_in[1];     // int32 (JAX x64 disabled)
    const float* W1   = (const float*)d_in[2];
    const float* b1   = (const float*)d_in[3];
    const float* W2   = (const float*)d_in[4];
    const float* b2   = (const float*)d_in[5];
    float* out        = (float*)d_out;

    const int n = in_sizes[0] / IN_CH;       // 100000
    const int e = in_sizes[1] / 2;           // 3200000
    const int* src = ei;
    const int* dst = ei + e;

    const int TB = 256;
    int gb_n = (n + TB - 1) / TB;            // == NBLK
    int gb_e = (e + TB - 1) / TB;
    int gb_w = (n * 32 + TB - 1) / TB;       // warp-per-node kernels

    k_zero_cnt<<<gb_n, TB>>>(n);             // 1
    k_hist<<<gb_e, TB>>>(dst, e);            // 2
    k_scan<<<gb_n, TB>>>(n);                 // 3
    k_scatter<<<gb_e, TB>>>(src, dst, e);    // 4  <-- profiled (control)
    k_gemm1<<<gb_n, 256>>>(x, W1, n);        // 5
    k_gather1<<<gb_w, TB>>>(b1, n);          // 6
    k_gather2<<<gb_w, TB>>>(W2, b2, out, n); // 7
}

// round 14
// speedup vs baseline: 1.3807x; 1.3807x over previous
#include <cuda_runtime.h>
#include <cstdint>

#define N_NODES 100000
#define IN_CH   512
#define HID     16
#define OUT_CH  64
#define MAX_E   3200000
#define NBLK    ((N_NODES + 255) / 256)   // 391 scan blocks

typedef unsigned long long u64;

// ---------------- device scratch (static, no allocation) ----------------
__device__ float g_dinv[N_NODES];
__device__ int   g_cnt[N_NODES];
__device__ u64   g_bstate[NBLK];          // decoupled-lookback state
__device__ int   g_rowptr[N_NODES + 1];
__device__ int   g_cur[N_NODES];
__device__ int   g_csr[MAX_E];            // src only, bucketed by dst
__device__ float g_h1[N_NODES * HID];     // h1' = (x@W1) * dinv   (pre-scaled)
__device__ float g_hr[N_NODES * HID];     // hr' = relu(conv1) * dinv (pre-scaled)

// ---------------- f32x2 / cp.async helpers ----------------
__device__ __forceinline__ u64 pack2(float lo, float hi) {
    u64 r; asm("mov.b64 %0, {%1, %2};" : "=l"(r) : "f"(lo), "f"(hi)); return r;
}
__device__ __forceinline__ u64 fma2(u64 a, u64 b, u64 c) {
    u64 d; asm("fma.rn.f32x2 %0, %1, %2, %3;" : "=l"(d) : "l"(a), "l"(b), "l"(c)); return d;
}
__device__ __forceinline__ float2 unpack2(u64 v) {
    float2 f; asm("mov.b64 {%0, %1}, %2;" : "=f"(f.x), "=f"(f.y) : "l"(v)); return f;
}
__device__ __forceinline__ void cpasync16(uint32_t saddr, const void* g, int srcbytes) {
    asm volatile("cp.async.cg.shared.global [%0], [%1], 16, %2;"
                 :: "r"(saddr), "l"(g), "r"(srcbytes));
}
__device__ __forceinline__ void cp_commit() {
    asm volatile("cp.async.commit_group;");
}
template <int N>
__device__ __forceinline__ void cp_wait() {
    asm volatile("cp.async.wait_group %0;" :: "n"(N));
}

// ---------------- GEMM1: h1' = (x @ W1) * dinv, k-pair f32x2, cp.async ----------------
#define XS_PITCH 20
#define NCHUNK   (IN_CH / 16)   // 32
__global__ void __launch_bounds__(256, 3) k_gemm1(const float* __restrict__ x,
                                                  const float* __restrict__ W, int n) {
    __shared__ __align__(16) float xs[2][256 * XS_PITCH];  // 2 x 20 KB
    __shared__ __align__(16) u64   wp[2][8 * HID];         // 2 x 1 KB

    const int t = threadIdx.x;
    const int rowBase = blockIdx.x * 256;
    const int rg = t >> 2;
    const int jg = t & 3;
    const int ko = (t & 3) * 4;

    auto stage_x = [&](int kk, int b) {
#pragma unroll
        for (int p = 0; p < 4; p++) {
            int row = (t >> 2) + p * 64;
            int grow = rowBase + row;
            bool ok = (grow < n);
            const float* gp = ok ? &x[(size_t)grow * IN_CH + kk + ko] : x;
            uint32_t sa = (uint32_t)__cvta_generic_to_shared(&xs[b][row * XS_PITCH + ko]);
            cpasync16(sa, gp, ok ? 16 : 0);
        }
    };
    auto stage_w = [&](int kk, int b) {
        if (t < 128) {
            int kp = t >> 4, j = t & 15;
            wp[b][kp * HID + j] = pack2(W[(kk + 2 * kp) * HID + j],
                                        W[(kk + 2 * kp + 1) * HID + j]);
        }
    };

    u64 acc[4][4];
#pragma unroll
    for (int r = 0; r < 4; r++)
#pragma unroll
        for (int j = 0; j < 4; j++) acc[r][j] = 0ull;

    stage_x(0, 0);
    stage_w(0, 0);
    cp_commit();

    int buf = 0;
    for (int c = 0; c < NCHUNK; c++) {
        if (c < NCHUNK - 1) {
            stage_x((c + 1) * 16, buf ^ 1);
            stage_w((c + 1) * 16, buf ^ 1);
            cp_commit();
            cp_wait<1>();
        } else {
            cp_wait<0>();
        }
        __syncthreads();

#pragma unroll
        for (int k4 = 0; k4 < 4; k4++) {
            u64 w0[4], w1[4];
            *reinterpret_cast<ulonglong2*>(&w0[0]) =
                *reinterpret_cast<const ulonglong2*>(&wp[buf][(2 * k4) * HID + jg * 4]);
            *reinterpret_cast<ulonglong2*>(&w0[2]) =
                *reinterpret_cast<const ulonglong2*>(&wp[buf][(2 * k4) * HID + jg * 4 + 2]);
            *reinterpret_cast<ulonglong2*>(&w1[0]) =
                *reinterpret_cast<const ulonglong2*>(&wp[buf][(2 * k4 + 1) * HID + jg * 4]);
            *reinterpret_cast<ulonglong2*>(&w1[2]) =
                *reinterpret_cast<const ulonglong2*>(&wp[buf][(2 * k4 + 1) * HID + jg * 4 + 2]);
#pragma unroll
            for (int r = 0; r < 4; r++) {
                ulonglong2 xq = *reinterpret_cast<const ulonglong2*>(
                    &xs[buf][(rg + 64 * r) * XS_PITCH + k4 * 4]);
#pragma unroll
                for (int j = 0; j < 4; j++) {
                    acc[r][j] = fma2(xq.x, w0[j], acc[r][j]);
                    acc[r][j] = fma2(xq.y, w1[j], acc[r][j]);
                }
            }
        }
        __syncthreads();
        buf ^= 1;
    }
#pragma unroll
    for (int r = 0; r < 4; r++) {
        int grow = rowBase + rg + 64 * r;
        if (grow < n) {
            float di = g_dinv[grow];
            float2 a0 = unpack2(acc[r][0]);
            float2 a1 = unpack2(acc[r][1]);
            float2 a2 = unpack2(acc[r][2]);
            float2 a3 = unpack2(acc[r][3]);
            reinterpret_cast<float4*>(&g_h1[(size_t)grow * HID])[jg] =
                make_float4((a0.x + a0.y) * di, (a1.x + a1.y) * di,
                            (a2.x + a2.y) * di, (a3.x + a3.y) * di);
        }
    }
}

// ---------------- CSR build ----------------
__global__ void k_zero_cnt(int n) {
    int i = blockIdx.x * blockDim.x + threadIdx.x;
    if (i < n) g_cnt[i] = 0;
    if (i < NBLK) g_bstate[i] = 0ull;
}

__global__ void k_hist(const int* __restrict__ dst, int e) {
    int i = blockIdx.x * blockDim.x + threadIdx.x;
    if (i < e) atomicAdd(&g_cnt[dst[i]], 1);
}

// single-kernel exclusive scan via decoupled lookback (flag+value in one u64)
__global__ void __launch_bounds__(256) k_scan(int n) {
    __shared__ int s[256];
    __shared__ int s_prefix;
    const int t = threadIdx.x, b = blockIdx.x;
    const int i = b * 256 + t;
    int v = (i < n) ? g_cnt[i] : 0;
    s[t] = v;
    __syncthreads();
#pragma unroll
    for (int off = 1; off < 256; off <<= 1) {
        int add = (t >= off) ? s[t - off] : 0;
        __syncthreads();
        s[t] += add;
        __syncthreads();
    }
    int incl = s[t];
    int agg  = s[255];

    if (t == 0) {
        u64 pk = (b == 0) ? ((2ull << 40) | (unsigned)agg)
                          : ((1ull << 40) | (unsigned)agg);
        atomicExch(&g_bstate[b], pk);
        if (b == 0) s_prefix = 0;
    }
    if (b > 0 && t < 32) {
        int ex = 0;
        int base = b;
        while (true) {
            int p = base - 32 + t;
            u64 st = (p >= 0) ? atomicAdd(&g_bstate[p], 0ull) : (2ull << 40);
            int flag = (int)(st >> 40);
            int val  = (int)(st & 0xFFFFFFFFu);
            if (!__all_sync(0xffffffffu, flag != 0)) continue;
            unsigned pm = __ballot_sync(0xffffffffu, flag == 2);
            int hi = pm ? (31 - __clz(pm)) : 0;
            int contrib = (pm == 0 || t >= hi) ? val : 0;
#pragma unroll
            for (int o = 16; o; o >>= 1)
                contrib += __shfl_xor_sync(0xffffffffu, contrib, o);
            ex += contrib;
            if (pm) break;
            base -= 32;
        }
        if (t == 0) {
            s_prefix = ex;
            atomicExch(&g_bstate[b], (2ull << 40) | (unsigned)(ex + agg));
        }
    }
    __syncthreads();
    if (i < n) {
        int rp = s_prefix + incl - v;
        g_rowptr[i] = rp;
        g_cur[i] = rp;
        g_dinv[i] = rsqrtf((float)v + 1.0f);
        if (i == n - 1) g_rowptr[n] = rp + v;
    }
}

__global__ void k_scatter(const int* __restrict__ src,
                          const int* __restrict__ dst, int e) {
    int i = blockIdx.x * blockDim.x + threadIdx.x;
    if (i >= e) return;
    int d = dst[i];
    int pos = atomicAdd(&g_cur[d], 1);
    g_csr[pos] = src[i];
}

// ---------------- gather layer 1: 2x-unrolled for MLP ----------------
__global__ void __launch_bounds__(256) k_gather1(const float* __restrict__ b1, int n) {
    int wid = (blockIdx.x * 256 + threadIdx.x) >> 5;
    if (wid >= n) return;
    int lane = threadIdx.x & 31;
    int ql = lane & 7, qh = lane >> 3;
    int row = g_rowptr[wid], end = g_rowptr[wid + 1];

    float2 acc = make_float2(0.f, 0.f);
    int i = row + qh;
    for (; i + 4 < end; i += 8) {          // two edges per iteration
        int s0 = g_csr[i];
        int s1 = g_csr[i + 4];
        float2 a = *reinterpret_cast<const float2*>(&g_h1[(size_t)s0 * HID + ql * 2]);
        float2 b = *reinterpret_cast<const float2*>(&g_h1[(size_t)s1 * HID + ql * 2]);
        acc.x += a.x + b.x;
        acc.y += a.y + b.y;
    }
    if (i < end) {
        int s0 = g_csr[i];
        float2 a = *reinterpret_cast<const float2*>(&g_h1[(size_t)s0 * HID + ql * 2]);
        acc.x += a.x;
        acc.y += a.y;
    }
    acc.x += __shfl_xor_sync(0xffffffffu, acc.x, 8);
    acc.y += __shfl_xor_sync(0xffffffffu, acc.y, 8);
    acc.x += __shfl_xor_sync(0xffffffffu, acc.x, 16);
    acc.y += __shfl_xor_sync(0xffffffffu, acc.y, 16);

    float di = g_dinv[wid];
    float2 hv = *reinterpret_cast<const float2*>(&g_h1[(size_t)wid * HID + ql * 2]);
    float2 bb = *reinterpret_cast<const float2*>(&b1[ql * 2]);
    float2 r;
    r.x = fmaxf(di * (acc.x + hv.x) + bb.x, 0.f) * di;   // pre-scale for layer 2
    r.y = fmaxf(di * (acc.y + hv.y) + bb.y, 0.f) * di;
    if (qh == 0)
        *reinterpret_cast<float2*>(&g_hr[(size_t)wid * HID + ql * 2]) = r;
}

// ---------------- gather layer 2: 2x-unrolled, fused W2 GEMM + log-softmax ----------------
__global__ void __launch_bounds__(256) k_gather2(const float* __restrict__ W2,
                                                 const float* __restrict__ b2,
                                                 float* __restrict__ out, int n) {
    __shared__ float W2s[HID * OUT_CH];  // 4 KB
    for (int i = threadIdx.x; i < HID * OUT_CH; i += 256) W2s[i] = W2[i];
    __syncthreads();

    int wid = (blockIdx.x * 256 + threadIdx.x) >> 5;
    if (wid >= n) return;
    int lane = threadIdx.x & 31;
    int ql = lane & 7, qh = lane >> 3;
    int row = g_rowptr[wid], end = g_rowptr[wid + 1];

    float2 acc = make_float2(0.f, 0.f);
    int i = row + qh;
    for (; i + 4 < end; i += 8) {
        int s0 = g_csr[i];
        int s1 = g_csr[i + 4];
        float2 a = *reinterpret_cast<const float2*>(&g_hr[(size_t)s0 * HID + ql * 2]);
        float2 b = *reinterpret_cast<const float2*>(&g_hr[(size_t)s1 * HID + ql * 2]);
        acc.x += a.x + b.x;
        acc.y += a.y + b.y;
    }
    if (i < end) {
        int s0 = g_csr[i];
        float2 a = *reinterpret_cast<const float2*>(&g_hr[(size_t)s0 * HID + ql * 2]);
        acc.x += a.x;
        acc.y += a.y;
    }
    acc.x += __shfl_xor_sync(0xffffffffu, acc.x, 8);
    acc.y += __shfl_xor_sync(0xffffffffu, acc.y, 8);
    acc.x += __shfl_xor_sync(0xffffffffu, acc.x, 16);
    acc.y += __shfl_xor_sync(0xffffffffu, acc.y, 16);

    float di = g_dinv[wid];
    float2 hv = *reinterpret_cast<const float2*>(&g_hr[(size_t)wid * HID + ql * 2]);
    float tx = di * (acc.x + hv.x);   // t[2*ql] (lanes 0..7 hold the 16-dim vector)
    float ty = di * (acc.y + hv.y);   // t[2*ql+1]

    float y0 = b2[lane];
    float y1 = b2[lane + 32];
#pragma unroll
    for (int k = 0; k < 8; k++) {
        float a = __shfl_sync(0xffffffffu, tx, k);
        float b = __shfl_sync(0xffffffffu, ty, k);
        y0 += a * W2s[(2 * k) * OUT_CH + lane]      + b * W2s[(2 * k + 1) * OUT_CH + lane];
        y1 += a * W2s[(2 * k) * OUT_CH + lane + 32] + b * W2s[(2 * k + 1) * OUT_CH + lane + 32];
    }
    float m = fmaxf(y0, y1);
#pragma unroll
    for (int o = 16; o; o >>= 1) m = fmaxf(m, __shfl_xor_sync(0xffffffffu, m, o));
    float se = expf(y0 - m) + expf(y1 - m);
#pragma unroll
    for (int o = 16; o; o >>= 1) se += __shfl_xor_sync(0xffffffffu, se, o);
    float lg = m + logf(se);
    out[(size_t)wid * OUT_CH + lane]      = y0 - lg;
    out[(size_t)wid * OUT_CH + lane + 32] = y1 - lg;
}

// ---------------- launch ----------------
extern "C" void kernel_launch(void* const* d_in, const int* in_sizes, int n_in,
                              void* d_out, int out_size) {
    const float* x    = (const float*)d_in[0];
    const int*   ei   = (const int*)d_in[1];     // int32 (JAX x64 disabled)
    const float* W1   = (const float*)d_in[2];
    const float* b1   = (const float*)d_in[3];
    const float* W2   = (const float*)d_in[4];
    const float* b2   = (const float*)d_in[5];
    float* out        = (float*)d_out;

    const int n = in_sizes[0] / IN_CH;       // 100000
    const int e = in_sizes[1] / 2;           // 3200000
    const int* src = ei;
    const int* dst = ei + e;

    const int TB = 256;
    int gb_n = (n + TB - 1) / TB;            // == NBLK
    int gb_e = (e + TB - 1) / TB;
    int gb_w = (n * 32 + TB - 1) / TB;       // warp-per-node kernels

    k_zero_cnt<<<gb_n, TB>>>(n);             // 1
    k_hist<<<gb_e, TB>>>(dst, e);            // 2
    k_scan<<<gb_n, TB>>>(n);                 // 3
    k_scatter<<<gb_e, TB>>>(src, dst, e);    // 4  <-- profiled (control)
    k_gemm1<<<gb_n, 256>>>(x, W1, n);        // 5
    k_gather1<<<gb_w, TB>>>(b1, n);          // 6
    k_gather2<<<gb_w, TB>>>(W2, b2, out, n); // 7
}

// round 15
// speedup vs baseline: 1.4924x; 1.0809x over previous
#include <cuda_runtime.h>
#include <cstdint>

#define N_NODES 100000
#define IN_CH   512
#define HID     16
#define OUT_CH  64
#define MAX_E   3200000
#define NBLK    ((N_NODES + 255) / 256)   // 391 gemm tiles / scan blocks

typedef unsigned long long u64;

// ---------------- device scratch (static, no allocation) ----------------
__device__ float g_dinv[N_NODES];
__device__ int   g_cnt[N_NODES];
__device__ u64   g_bstate[NBLK];          // decoupled-lookback state
__device__ int   g_rowptr[N_NODES + 1];
__device__ int   g_cur[N_NODES];
__device__ int   g_csr[MAX_E];            // src only, bucketed by dst
__device__ float g_h1[N_NODES * HID];     // h1' = (x@W1) * dinv   (pre-scaled)
__device__ float g_hr[N_NODES * HID];     // hr' = relu(conv1) * dinv (pre-scaled)

// ---------------- f32x2 / cp.async helpers ----------------
__device__ __forceinline__ u64 pack2(float lo, float hi) {
    u64 r; asm("mov.b64 %0, {%1, %2};" : "=l"(r) : "f"(lo), "f"(hi)); return r;
}
__device__ __forceinline__ u64 fma2(u64 a, u64 b, u64 c) {
    u64 d; asm("fma.rn.f32x2 %0, %1, %2, %3;" : "=l"(d) : "l"(a), "l"(b), "l"(c)); return d;
}
__device__ __forceinline__ float2 unpack2(u64 v) {
    float2 f; asm("mov.b64 {%0, %1}, %2;" : "=f"(f.x), "=f"(f.y) : "l"(v)); return f;
}
__device__ __forceinline__ void cpasync16(uint32_t saddr, const void* g, int srcbytes) {
    asm volatile("cp.async.cg.shared.global [%0], [%1], 16, %2;"
                 :: "r"(saddr), "l"(g), "r"(srcbytes));
}
__device__ __forceinline__ void cp_commit() {
    asm volatile("cp.async.commit_group;");
}
template <int N>
__device__ __forceinline__ void cp_wait() {
    asm volatile("cp.async.wait_group %0;" :: "n"(N));
}

// ---------------- GEMM1 tile body: h1' = (x @ W1) * dinv ----------------
#define XS_PITCH 20
#define NCHUNK   (IN_CH / 16)   // 32
__device__ __forceinline__ void gemm1_tile(const float* __restrict__ x,
                                           const float* __restrict__ W,
                                           int n, int tile) {
    __shared__ __align__(16) float xs[2][256 * XS_PITCH];  // 2 x 20 KB
    __shared__ __align__(16) u64   wp[2][8 * HID];         // 2 x 1 KB

    const int t = threadIdx.x;
    const int rowBase = tile * 256;
    const int rg = t >> 2;
    const int jg = t & 3;
    const int ko = (t & 3) * 4;

    auto stage_x = [&](int kk, int b) {
#pragma unroll
        for (int p = 0; p < 4; p++) {
            int row = (t >> 2) + p * 64;
            int grow = rowBase + row;
            bool ok = (grow < n);
            const float* gp = ok ? &x[(size_t)grow * IN_CH + kk + ko] : x;
            uint32_t sa = (uint32_t)__cvta_generic_to_shared(&xs[b][row * XS_PITCH + ko]);
            cpasync16(sa, gp, ok ? 16 : 0);
        }
    };
    auto stage_w = [&](int kk, int b) {
        if (t < 128) {
            int kp = t >> 4, j = t & 15;
            wp[b][kp * HID + j] = pack2(W[(kk + 2 * kp) * HID + j],
                                        W[(kk + 2 * kp + 1) * HID + j]);
        }
    };

    u64 acc[4][4];
#pragma unroll
    for (int r = 0; r < 4; r++)
#pragma unroll
        for (int j = 0; j < 4; j++) acc[r][j] = 0ull;

    stage_x(0, 0);
    stage_w(0, 0);
    cp_commit();

    int buf = 0;
    for (int c = 0; c < NCHUNK; c++) {
        if (c < NCHUNK - 1) {
            stage_x((c + 1) * 16, buf ^ 1);
            stage_w((c + 1) * 16, buf ^ 1);
            cp_commit();
            cp_wait<1>();
        } else {
            cp_wait<0>();
        }
        __syncthreads();

#pragma unroll
        for (int k4 = 0; k4 < 4; k4++) {
            u64 w0[4], w1[4];
            *reinterpret_cast<ulonglong2*>(&w0[0]) =
                *reinterpret_cast<const ulonglong2*>(&wp[buf][(2 * k4) * HID + jg * 4]);
            *reinterpret_cast<ulonglong2*>(&w0[2]) =
                *reinterpret_cast<const ulonglong2*>(&wp[buf][(2 * k4) * HID + jg * 4 + 2]);
            *reinterpret_cast<ulonglong2*>(&w1[0]) =
                *reinterpret_cast<const ulonglong2*>(&wp[buf][(2 * k4 + 1) * HID + jg * 4]);
            *reinterpret_cast<ulonglong2*>(&w1[2]) =
                *reinterpret_cast<const ulonglong2*>(&wp[buf][(2 * k4 + 1) * HID + jg * 4 + 2]);
#pragma unroll
            for (int r = 0; r < 4; r++) {
                ulonglong2 xq = *reinterpret_cast<const ulonglong2*>(
                    &xs[buf][(rg + 64 * r) * XS_PITCH + k4 * 4]);
#pragma unroll
                for (int j = 0; j < 4; j++) {
                    acc[r][j] = fma2(xq.x, w0[j], acc[r][j]);
                    acc[r][j] = fma2(xq.y, w1[j], acc[r][j]);
                }
            }
        }
        __syncthreads();
        buf ^= 1;
    }
#pragma unroll
    for (int r = 0; r < 4; r++) {
        int grow = rowBase + rg + 64 * r;
        if (grow < n) {
            float di = g_dinv[grow];
            float2 a0 = unpack2(acc[r][0]);
            float2 a1 = unpack2(acc[r][1]);
            float2 a2 = unpack2(acc[r][2]);
            float2 a3 = unpack2(acc[r][3]);
            reinterpret_cast<float4*>(&g_h1[(size_t)grow * HID])[jg] =
                make_float4((a0.x + a0.y) * di, (a1.x + a1.y) * di,
                            (a2.x + a2.y) * di, (a3.x + a3.y) * di);
        }
    }
}

// ---------------- combined kernel: gemm tiles [0,NBLK) + scatter blocks after ----------------
__global__ void __launch_bounds__(256) k_ck(const float* __restrict__ x,
                                            const float* __restrict__ W,
                                            const int* __restrict__ src,
                                            const int* __restrict__ dst,
                                            int n, int e) {
    if ((int)blockIdx.x < NBLK) {
        gemm1_tile(x, W, n, blockIdx.x);
    } else {
        int i = ((int)blockIdx.x - NBLK) * 256 + threadIdx.x;
        if (i < e) {
            int d = dst[i];
            int pos = atomicAdd(&g_cur[d], 1);
            g_csr[pos] = src[i];
        }
    }
}

// ---------------- CSR build ----------------
__global__ void k_zero_cnt(int n) {
    int i = blockIdx.x * blockDim.x + threadIdx.x;
    if (i < n) g_cnt[i] = 0;
    if (i < NBLK) g_bstate[i] = 0ull;
}

__global__ void k_hist(const int* __restrict__ dst, int e) {
    int i = blockIdx.x * blockDim.x + threadIdx.x;
    if (i < e) atomicAdd(&g_cnt[dst[i]], 1);
}

// single-kernel exclusive scan via decoupled lookback (flag+value in one u64)
__global__ void __launch_bounds__(256) k_scan(int n) {
    __shared__ int s[256];
    __shared__ int s_prefix;
    const int t = threadIdx.x, b = blockIdx.x;
    const int i = b * 256 + t;
    int v = (i < n) ? g_cnt[i] : 0;
    s[t] = v;
    __syncthreads();
#pragma unroll
    for (int off = 1; off < 256; off <<= 1) {
        int add = (t >= off) ? s[t - off] : 0;
        __syncthreads();
        s[t] += add;
        __syncthreads();
    }
    int incl = s[t];
    int agg  = s[255];

    if (t == 0) {
        u64 pk = (b == 0) ? ((2ull << 40) | (unsigned)agg)
                          : ((1ull << 40) | (unsigned)agg);
        atomicExch(&g_bstate[b], pk);
        if (b == 0) s_prefix = 0;
    }
    if (b > 0 && t < 32) {
        int ex = 0;
        int base = b;
        while (true) {
            int p = base - 32 + t;
            u64 st = (p >= 0) ? atomicAdd(&g_bstate[p], 0ull) : (2ull << 40);
            int flag = (int)(st >> 40);
            int val  = (int)(st & 0xFFFFFFFFu);
            if (!__all_sync(0xffffffffu, flag != 0)) continue;
            unsigned pm = __ballot_sync(0xffffffffu, flag == 2);
            int hi = pm ? (31 - __clz(pm)) : 0;
            int contrib = (pm == 0 || t >= hi) ? val : 0;
#pragma unroll
            for (int o = 16; o; o >>= 1)
                contrib += __shfl_xor_sync(0xffffffffu, contrib, o);
            ex += contrib;
            if (pm) break;
            base -= 32;
        }
        if (t == 0) {
            s_prefix = ex;
            atomicExch(&g_bstate[b], (2ull << 40) | (unsigned)(ex + agg));
        }
    }
    __syncthreads();
    if (i < n) {
        int rp = s_prefix + incl - v;
        g_rowptr[i] = rp;
        g_cur[i] = rp;
        g_dinv[i] = rsqrtf((float)v + 1.0f);
        if (i == n - 1) g_rowptr[n] = rp + v;
    }
}

// ---------------- gather layer 1 ----------------
__global__ void __launch_bounds__(256) k_gather1(const float* __restrict__ b1, int n) {
    int wid = (blockIdx.x * 256 + threadIdx.x) >> 5;
    if (wid >= n) return;
    int lane = threadIdx.x & 31;
    int ql = lane & 7, qh = lane >> 3;
    int row = g_rowptr[wid], end = g_rowptr[wid + 1];

    float2 acc = make_float2(0.f, 0.f);
    for (int i = row + qh; i < end; i += 4) {
        int s = g_csr[i];
        float2 hv = *reinterpret_cast<const float2*>(&g_h1[(size_t)s * HID + ql * 2]);
        acc.x += hv.x;
        acc.y += hv.y;
    }
    acc.x += __shfl_xor_sync(0xffffffffu, acc.x, 8);
    acc.y += __shfl_xor_sync(0xffffffffu, acc.y, 8);
    acc.x += __shfl_xor_sync(0xffffffffu, acc.x, 16);
    acc.y += __shfl_xor_sync(0xffffffffu, acc.y, 16);

    float di = g_dinv[wid];
    float2 hv = *reinterpret_cast<const float2*>(&g_h1[(size_t)wid * HID + ql * 2]);
    float2 bb = *reinterpret_cast<const float2*>(&b1[ql * 2]);
    float2 r;
    r.x = fmaxf(di * (acc.x + hv.x) + bb.x, 0.f) * di;   // pre-scale for layer 2
    r.y = fmaxf(di * (acc.y + hv.y) + bb.y, 0.f) * di;
    if (qh == 0)
        *reinterpret_cast<float2*>(&g_hr[(size_t)wid * HID + ql * 2]) = r;
}

// ---------------- gather layer 2 (fused W2 GEMM + log-softmax) ----------------
__global__ void __launch_bounds__(256) k_gather2(const float* __restrict__ W2,
                                                 const float* __restrict__ b2,
                                                 float* __restrict__ out, int n) {
    __shared__ float W2s[HID * OUT_CH];  // 4 KB
    for (int i = threadIdx.x; i < HID * OUT_CH; i += 256) W2s[i] = W2[i];
    __syncthreads();

    int wid = (blockIdx.x * 256 + threadIdx.x) >> 5;
    if (wid >= n) return;
    int lane = threadIdx.x & 31;
    int ql = lane & 7, qh = lane >> 3;
    int row = g_rowptr[wid], end = g_rowptr[wid + 1];

    float2 acc = make_float2(0.f, 0.f);
    for (int i = row + qh; i < end; i += 4) {
        int s = g_csr[i];
        float2 hv = *reinterpret_cast<const float2*>(&g_hr[(size_t)s * HID + ql * 2]);
        acc.x += hv.x;
        acc.y += hv.y;
    }
    acc.x += __shfl_xor_sync(0xffffffffu, acc.x, 8);
    acc.y += __shfl_xor_sync(0xffffffffu, acc.y, 8);
    acc.x += __shfl_xor_sync(0xffffffffu, acc.x, 16);
    acc.y += __shfl_xor_sync(0xffffffffu, acc.y, 16);

    float di = g_dinv[wid];
    float2 hv = *reinterpret_cast<const float2*>(&g_hr[(size_t)wid * HID + ql * 2]);
    float tx = di * (acc.x + hv.x);   // t[2*ql] (lanes 0..7 hold the 16-dim vector)
    float ty = di * (acc.y + hv.y);   // t[2*ql+1]

    float y0 = b2[lane];
    float y1 = b2[lane + 32];
#pragma unroll
    for (int k = 0; k < 8; k++) {
        float a = __shfl_sync(0xffffffffu, tx, k);
        float b = __shfl_sync(0xffffffffu, ty, k);
        y0 += a * W2s[(2 * k) * OUT_CH + lane]      + b * W2s[(2 * k + 1) * OUT_CH + lane];
        y1 += a * W2s[(2 * k) * OUT_CH + lane + 32] + b * W2s[(2 * k + 1) * OUT_CH + lane + 32];
    }
    float m = fmaxf(y0, y1);
#pragma unroll
    for (int o = 16; o; o >>= 1) m = fmaxf(m, __shfl_xor_sync(0xffffffffu, m, o));
    float se = expf(y0 - m) + expf(y1 - m);
#pragma unroll
    for (int o = 16; o; o >>= 1) se += __shfl_xor_sync(0xffffffffu, se, o);
    float lg = m + logf(se);
    out[(size_t)wid * OUT_CH + lane]      = y0 - lg;
    out[(size_t)wid * OUT_CH + lane + 32] = y1 - lg;
}

// ---------------- launch ----------------
extern "C" void kernel_launch(void* const* d_in, const int* in_sizes, int n_in,
                              void* d_out, int out_size) {
    const float* x    = (const float*)d_in[0];
    const int*   ei   = (const int*)d_in[1];     // int32 (JAX x64 disabled)
    const float* W1   = (const float*)d_in[2];
    const float* b1   = (const float*)d_in[3];
    const float* W2   = (const float*)d_in[4];
    const float* b2   = (const float*)d_in[5];
    float* out        = (float*)d_out;

    const int n = in_sizes[0] / IN_CH;       // 100000
    const int e = in_sizes[1] / 2;           // 3200000
    const int* src = ei;
    const int* dst = ei + e;

    const int TB = 256;
    int gb_n = (n + TB - 1) / TB;            // == NBLK
    int gb_e = (e + TB - 1) / TB;            // 12500
    int gb_w = (n * 32 + TB - 1) / TB;       // warp-per-node kernels

    k_zero_cnt<<<gb_n, TB>>>(n);             // 1
    k_hist<<<gb_e, TB>>>(dst, e);            // 2
    k_scan<<<gb_n, TB>>>(n);                 // 3
    k_ck<<<NBLK + gb_e, TB>>>(x, W1, src, dst, n, e);  // 4  <-- profiled (gemm+scatter overlapped)
    k_gather1<<<gb_w, TB>>>(b1, n);          // 5
    k_gather2<<<gb_w, TB>>>(W2, b2, out, n); // 6
}

// round 16
// speedup vs baseline: 1.5081x; 1.0106x over previous
#include <cuda_runtime.h>
#include <cstdint>

#define N_NODES 100000
#define IN_CH   512
#define HID     16
#define OUT_CH  64
#define MAX_E   3200000
#define NBLK    ((N_NODES + 255) / 256)   // 391 gemm tiles / scan blocks

typedef unsigned long long u64;

// ---------------- device scratch (static, no allocation) ----------------
// invariant: g_cnt is all-zero at kernel_launch entry (zero-init first run;
// the scan phase re-zeroes it each run). g_c_scan likewise (reset by gather2).
__device__ float g_dinv[N_NODES];
__device__ int   g_cnt[N_NODES];
__device__ u64   g_bstate[NBLK];          // decoupled-lookback state (zeroed by k_hist)
__device__ int   g_rowptr[N_NODES + 1];
__device__ int   g_cur[N_NODES];
__device__ int   g_csr[MAX_E];            // src only, bucketed by dst
__device__ float g_h1[N_NODES * HID];     // h1' = (x@W1) * dinv   (pre-scaled)
__device__ float g_hr[N_NODES * HID];     // hr' = relu(conv1) * dinv (pre-scaled)
__device__ int   g_c_scan;                // completed scan blocks (release counter)

// ---------------- helpers ----------------
__device__ __forceinline__ u64 pack2(float lo, float hi) {
    u64 r; asm("mov.b64 %0, {%1, %2};" : "=l"(r) : "f"(lo), "f"(hi)); return r;
}
__device__ __forceinline__ u64 fma2(u64 a, u64 b, u64 c) {
    u64 d; asm("fma.rn.f32x2 %0, %1, %2, %3;" : "=l"(d) : "l"(a), "l"(b), "l"(c)); return d;
}
__device__ __forceinline__ float2 unpack2(u64 v) {
    float2 f; asm("mov.b64 {%0, %1}, %2;" : "=f"(f.x), "=f"(f.y) : "l"(v)); return f;
}
__device__ __forceinline__ void cpasync16(uint32_t saddr, const void* g, int srcbytes) {
    asm volatile("cp.async.cg.shared.global [%0], [%1], 16, %2;"
                 :: "r"(saddr), "l"(g), "r"(srcbytes));
}
__device__ __forceinline__ void cp_commit() {
    asm volatile("cp.async.commit_group;");
}
template <int N>
__device__ __forceinline__ void cp_wait() {
    asm volatile("cp.async.wait_group %0;" :: "n"(N));
}
__device__ __forceinline__ void spin_scan_done() {
    volatile int* p = &g_c_scan;
    while (*p < NBLK) __nanosleep(128);
}

// ---------------- GEMM1 tile: h1' = (x @ W1) * dinv (spin before epilogue) ----------------
#define XS_PITCH 20
#define NCHUNK   (IN_CH / 16)   // 32
__device__ __forceinline__ void gemm1_tile(const float* __restrict__ x,
                                           const float* __restrict__ W,
                                           int n, int tile) {
    __shared__ __align__(16) float xs[2][256 * XS_PITCH];  // 40 KB
    __shared__ __align__(16) u64   wp[2][8 * HID];         // 2 KB

    const int t = threadIdx.x;
    const int rowBase = tile * 256;
    const int rg = t >> 2;
    const int jg = t & 3;
    const int ko = (t & 3) * 4;

    auto stage_x = [&](int kk, int b) {
#pragma unroll
        for (int p = 0; p < 4; p++) {
            int row = (t >> 2) + p * 64;
            int grow = rowBase + row;
            bool ok = (grow < n);
            const float* gp = ok ? &x[(size_t)grow * IN_CH + kk + ko] : x;
            uint32_t sa = (uint32_t)__cvta_generic_to_shared(&xs[b][row * XS_PITCH + ko]);
            cpasync16(sa, gp, ok ? 16 : 0);
        }
    };
    auto stage_w = [&](int kk, int b) {
        if (t < 128) {
            int kp = t >> 4, j = t & 15;
            wp[b][kp * HID + j] = pack2(W[(kk + 2 * kp) * HID + j],
                                        W[(kk + 2 * kp + 1) * HID + j]);
        }
    };

    u64 acc[4][4];
#pragma unroll
    for (int r = 0; r < 4; r++)
#pragma unroll
        for (int j = 0; j < 4; j++) acc[r][j] = 0ull;

    stage_x(0, 0);
    stage_w(0, 0);
    cp_commit();

    int buf = 0;
    for (int c = 0; c < NCHUNK; c++) {
        if (c < NCHUNK - 1) {
            stage_x((c + 1) * 16, buf ^ 1);
            stage_w((c + 1) * 16, buf ^ 1);
            cp_commit();
            cp_wait<1>();
        } else {
            cp_wait<0>();
        }
        __syncthreads();

#pragma unroll
        for (int k4 = 0; k4 < 4; k4++) {
            u64 w0[4], w1[4];
            *reinterpret_cast<ulonglong2*>(&w0[0]) =
                *reinterpret_cast<const ulonglong2*>(&wp[buf][(2 * k4) * HID + jg * 4]);
            *reinterpret_cast<ulonglong2*>(&w0[2]) =
                *reinterpret_cast<const ulonglong2*>(&wp[buf][(2 * k4) * HID + jg * 4 + 2]);
            *reinterpret_cast<ulonglong2*>(&w1[0]) =
                *reinterpret_cast<const ulonglong2*>(&wp[buf][(2 * k4 + 1) * HID + jg * 4]);
            *reinterpret_cast<ulonglong2*>(&w1[2]) =
                *reinterpret_cast<const ulonglong2*>(&wp[buf][(2 * k4 + 1) * HID + jg * 4 + 2]);
#pragma unroll
            for (int r = 0; r < 4; r++) {
                ulonglong2 xq = *reinterpret_cast<const ulonglong2*>(
                    &xs[buf][(rg + 64 * r) * XS_PITCH + k4 * 4]);
#pragma unroll
                for (int j = 0; j < 4; j++) {
                    acc[r][j] = fma2(xq.x, w0[j], acc[r][j]);
                    acc[r][j] = fma2(xq.y, w1[j], acc[r][j]);
                }
            }
        }
        __syncthreads();
        buf ^= 1;
    }

    // wait for the in-kernel scan phase (dinv) — long done by now in practice
    if (t == 0) spin_scan_done();
    __syncthreads();

#pragma unroll
    for (int r = 0; r < 4; r++) {
        int grow = rowBase + rg + 64 * r;
        if (grow < n) {
            float di = g_dinv[grow];
            float2 a0 = unpack2(acc[r][0]);
            float2 a1 = unpack2(acc[r][1]);
            float2 a2 = unpack2(acc[r][2]);
            float2 a3 = unpack2(acc[r][3]);
            reinterpret_cast<float4*>(&g_h1[(size_t)grow * HID])[jg] =
                make_float4((a0.x + a0.y) * di, (a1.x + a1.y) * di,
                            (a2.x + a2.y) * di, (a3.x + a3.y) * di);
        }
    }
}

// ---------------- scan block body (decoupled lookback; zeroes g_cnt behind itself) ----------------
__device__ __forceinline__ void scan_block(int sb, int n) {
    __shared__ int s[256];
    __shared__ int s_prefix;
    const int t = threadIdx.x;
    const int i = sb * 256 + t;
    int v = (i < n) ? g_cnt[i] : 0;
    if (i < n) g_cnt[i] = 0;              // restore zero-invariant for next replay
    s[t] = v;
    __syncthreads();
#pragma unroll
    for (int off = 1; off < 256; off <<= 1) {
        int add = (t >= off) ? s[t - off] : 0;
        __syncthreads();
        s[t] += add;
        __syncthreads();
    }
    int incl = s[t];
    int agg  = s[255];

    if (t == 0) {
        u64 pk = (sb == 0) ? ((2ull << 40) | (unsigned)agg)
                           : ((1ull << 40) | (unsigned)agg);
        atomicExch(&g_bstate[sb], pk);
        if (sb == 0) s_prefix = 0;
    }
    if (sb > 0 && t < 32) {
        int ex = 0;
        int base = sb;
        while (true) {
            int p = base - 32 + t;
            u64 st = (p >= 0) ? atomicAdd(&g_bstate[p], 0ull) : (2ull << 40);
            int flag = (int)(st >> 40);
            int val  = (int)(st & 0xFFFFFFFFu);
            if (!__all_sync(0xffffffffu, flag != 0)) continue;
            unsigned pm = __ballot_sync(0xffffffffu, flag == 2);
            int hi = pm ? (31 - __clz(pm)) : 0;
            int contrib = (pm == 0 || t >= hi) ? val : 0;
#pragma unroll
            for (int o = 16; o; o >>= 1)
                contrib += __shfl_xor_sync(0xffffffffu, contrib, o);
            ex += contrib;
            if (pm) break;
            base -= 32;
        }
        if (t == 0) {
            s_prefix = ex;
            atomicExch(&g_bstate[sb], (2ull << 40) | (unsigned)(ex + agg));
        }
    }
    __syncthreads();
    if (i < n) {
        int rp = s_prefix + incl - v;
        g_rowptr[i] = rp;
        g_cur[i] = rp;
        g_dinv[i] = rsqrtf((float)v + 1.0f);
        if (i == n - 1) g_rowptr[n] = rp + v;
    }
    __threadfence();
    __syncthreads();
    if (t == 0) atomicAdd(&g_c_scan, 1);   // release
}

// ---------------- combined kernel: [gemm 391][scan 391][scatter] ----------------
__global__ void __launch_bounds__(256) k_ck(const float* __restrict__ x,
                                            const float* __restrict__ W,
                                            const int* __restrict__ src,
                                            const int* __restrict__ dst,
                                            int n, int e) {
    int b = blockIdx.x;
    if (b < NBLK) {
        gemm1_tile(x, W, n, b);
    } else if (b < 2 * NBLK) {
        scan_block(b - NBLK, n);
    } else {
        if (threadIdx.x == 0) spin_scan_done();
        __syncthreads();
        int i = (b - 2 * NBLK) * 256 + threadIdx.x;
        if (i < e) {
            int d = dst[i];
            int pos = atomicAdd(&g_cur[d], 1);
            g_csr[pos] = src[i];
        }
    }
}

// ---------------- hist (also zeroes lookback state for this run) ----------------
__global__ void k_hist(const int* __restrict__ dst, int e) {
    int b = blockIdx.x, t = threadIdx.x;
    if (b < 2) {
        int z = b * 256 + t;
        if (z < NBLK) g_bstate[z] = 0ull;
    }
    int i = b * 256 + t;
    if (i < e) atomicAdd(&g_cnt[dst[i]], 1);
}

// ---------------- gather layer 1 ----------------
__global__ void __launch_bounds__(256) k_gather1(const float* __restrict__ b1, int n) {
    int wid = (blockIdx.x * 256 + threadIdx.x) >> 5;
    if (wid >= n) return;
    int lane = threadIdx.x & 31;
    int ql = lane & 7, qh = lane >> 3;
    int row = g_rowptr[wid], end = g_rowptr[wid + 1];

    float2 acc = make_float2(0.f, 0.f);
    for (int i = row + qh; i < end; i += 4) {
        int s = g_csr[i];
        float2 hv = *reinterpret_cast<const float2*>(&g_h1[(size_t)s * HID + ql * 2]);
        acc.x += hv.x;
        acc.y += hv.y;
    }
    acc.x += __shfl_xor_sync(0xffffffffu, acc.x, 8);
    acc.y += __shfl_xor_sync(0xffffffffu, acc.y, 8);
    acc.x += __shfl_xor_sync(0xffffffffu, acc.x, 16);
    acc.y += __shfl_xor_sync(0xffffffffu, acc.y, 16);

    float di = g_dinv[wid];
    float2 hv = *reinterpret_cast<const float2*>(&g_h1[(size_t)wid * HID + ql * 2]);
    float2 bb = *reinterpret_cast<const float2*>(&b1[ql * 2]);
    float2 r;
    r.x = fmaxf(di * (acc.x + hv.x) + bb.x, 0.f) * di;   // pre-scale for layer 2
    r.y = fmaxf(di * (acc.y + hv.y) + bb.y, 0.f) * di;
    if (qh == 0)
        *reinterpret_cast<float2*>(&g_hr[(size_t)wid * HID + ql * 2]) = r;
}

// ---------------- gather layer 2 (fused W2 GEMM + log-softmax; resets counter) ----------------
__global__ void __launch_bounds__(256) k_gather2(const float* __restrict__ W2,
                                                 const float* __restrict__ b2,
                                                 float* __restrict__ out, int n) {
    __shared__ float W2s[HID * OUT_CH];  // 4 KB
    if (blockIdx.x == 0 && threadIdx.x == 0) g_c_scan = 0;   // reset for next replay
    for (int i = threadIdx.x; i < HID * OUT_CH; i += 256) W2s[i] = W2[i];
    __syncthreads();

    int wid = (blockIdx.x * 256 + threadIdx.x) >> 5;
    if (wid >= n) return;
    int lane = threadIdx.x & 31;
    int ql = lane & 7, qh = lane >> 3;
    int row = g_rowptr[wid], end = g_rowptr[wid + 1];

    float2 acc = make_float2(0.f, 0.f);
    for (int i = row + qh; i < end; i += 4) {
        int s = g_csr[i];
        float2 hv = *reinterpret_cast<const float2*>(&g_hr[(size_t)s * HID + ql * 2]);
        acc.x += hv.x;
        acc.y += hv.y;
    }
    acc.x += __shfl_xor_sync(0xffffffffu, acc.x, 8);
    acc.y += __shfl_xor_sync(0xffffffffu, acc.y, 8);
    acc.x += __shfl_xor_sync(0xffffffffu, acc.x, 16);
    acc.y += __shfl_xor_sync(0xffffffffu, acc.y, 16);

    float di = g_dinv[wid];
    float2 hv = *reinterpret_cast<const float2*>(&g_hr[(size_t)wid * HID + ql * 2]);
    float tx = di * (acc.x + hv.x);   // t[2*ql] (lanes 0..7 hold the 16-dim vector)
    float ty = di * (acc.y + hv.y);   // t[2*ql+1]

    float y0 = b2[lane];
    float y1 = b2[lane + 32];
#pragma unroll
    for (int k = 0; k < 8; k++) {
        float a = __shfl_sync(0xffffffffu, tx, k);
        float b = __shfl_sync(0xffffffffu, ty, k);
        y0 += a * W2s[(2 * k) * OUT_CH + lane]      + b * W2s[(2 * k + 1) * OUT_CH + lane];
        y1 += a * W2s[(2 * k) * OUT_CH + lane + 32] + b * W2s[(2 * k + 1) * OUT_CH + lane + 32];
    }
    float m = fmaxf(y0, y1);
#pragma unroll
    for (int o = 16; o; o >>= 1) m = fmaxf(m, __shfl_xor_sync(0xffffffffu, m, o));
    float se = expf(y0 - m) + expf(y1 - m);
#pragma unroll
    for (int o = 16; o; o >>= 1) se += __shfl_xor_sync(0xffffffffu, se, o);
    float lg = m + logf(se);
    out[(size_t)wid * OUT_CH + lane]      = y0 - lg;
    out[(size_t)wid * OUT_CH + lane + 32] = y1 - lg;
}

// ---------------- launch ----------------
extern "C" void kernel_launch(void* const* d_in, const int* in_sizes, int n_in,
                              void* d_out, int out_size) {
    const float* x    = (const float*)d_in[0];
    const int*   ei   = (const int*)d_in[1];     // int32 (JAX x64 disabled)
    const float* W1   = (const float*)d_in[2];
    const float* b1   = (const float*)d_in[3];
    const float* W2   = (const float*)d_in[4];
    const float* b2   = (const float*)d_in[5];
    float* out        = (float*)d_out;

    const int n = in_sizes[0] / IN_CH;       // 100000
    const int e = in_sizes[1] / 2;           // 3200000
    const int* src = ei;
    const int* dst = ei + e;

    const int TB = 256;
    int gb_e = (e + TB - 1) / TB;            // 12500
    int gb_w = (n * 32 + TB - 1) / TB;       // warp-per-node kernels

    k_hist<<<gb_e, TB>>>(dst, e);                          // 1
    k_ck<<<2 * NBLK + gb_e, TB>>>(x, W1, src, dst, n, e);  // 2 (gemm+scan+scatter)
    k_gather1<<<gb_w, TB>>>(b1, n);                        // 3
    k_gather2<<<gb_w, TB>>>(W2, b2, out, n);               // 4 <-- profiled
}